// round 12
// baseline (speedup 1.0000x reference)
#include <cuda_runtime.h>
#include <cuda_bf16.h>
#include <math.h>
#include <stdint.h>

// ---------------- problem constants ----------------
#define BATCH      512
#define INPUT_DIM  1536
#define MAMBA_DIM  1024
#define OUTPUT_DIM 1024
#define D_STATE    128
#define D_CONV     4
#define HEADDIM    64
#define D_INNER    2048
#define NHEADS     32
#define CONV_DIM   2304          // D_INNER + 2*D_STATE
#define D_IN_PROJ  4384          // 2*D_INNER + 2*D_STATE + NHEADS
#define EPS        1e-5f
#define SPLITS     4
#define BC_DIM     (2 * D_STATE)             // 256

// output regions (floats)
#define OUT_Y_OFF    0
#define OUT_CONV_OFF (BATCH * OUTPUT_DIM)                       // 524288
#define OUT_SSM_OFF  (OUT_CONV_OFF + BATCH * CONV_DIM * D_CONV) // 5242880

// ---------------- scratch (global device arrays, no allocation) ----------------
__device__ float g_h   [BATCH * MAMBA_DIM];            // silu(rmsnorm(...))
__device__ float g_zx  [BATCH * D_IN_PROJ];            // zxbcdt
__device__ float g_bc  [BATCH * BC_DIM];               // silu(conv) of B/C channels
__device__ float g_ybuf[BATCH * D_INNER];              // gated y before out proj
__device__ float g_t2  [BATCH * MAMBA_DIM];            // y@W_mamba_out
__device__ float g_part[SPLITS * BATCH * MAMBA_DIM];   // split-K partials (8MB)

// ---------------- helpers ----------------
__device__ __forceinline__ float siluf(float v) { return v / (1.f + expf(-v)); }

__device__ __forceinline__ uint32_t f2tf32(float f) {
    uint32_t u;
    asm("cvt.rna.tf32.f32 %0, %1;" : "=r"(u) : "f"(f));
    return u;
}

__device__ __forceinline__ void mma_tf32(float* c,
                                         uint32_t a0, uint32_t a1, uint32_t a2, uint32_t a3,
                                         uint32_t b0, uint32_t b1) {
    asm volatile(
        "mma.sync.aligned.m16n8k8.row.col.f32.tf32.tf32.f32 "
        "{%0,%1,%2,%3}, {%4,%5,%6,%7}, {%8,%9}, {%0,%1,%2,%3};"
        : "+f"(c[0]), "+f"(c[1]), "+f"(c[2]), "+f"(c[3])
        : "r"(a0), "r"(a1), "r"(a2), "r"(a3), "r"(b0), "r"(b1));
}

__device__ __forceinline__ void cp_async16(void* smem_dst, const void* gsrc) {
    uint32_t d = (uint32_t)__cvta_generic_to_shared(smem_dst);
    asm volatile("cp.async.cg.shared.global [%0], [%1], 16;\n" :: "r"(d), "l"(gsrc));
}
__device__ __forceinline__ void cp_async16z(void* smem_dst, const void* gsrc, int src_bytes) {
    uint32_t d = (uint32_t)__cvta_generic_to_shared(smem_dst);
    asm volatile("cp.async.cg.shared.global [%0], [%1], 16, %2;\n"
                 :: "r"(d), "l"(gsrc), "r"(src_bytes));
}
#define CP_COMMIT() asm volatile("cp.async.commit_group;\n" ::: "memory")
#define CP_WAIT1()  asm volatile("cp.async.wait_group 1;\n" ::: "memory")

// ---------------- TF32 tensor-core GEMM, 3-stage cp.async pipeline (round-9 proven) ----------------
template <int BM, int BN, int MI, int NI, bool SPLIT>
__global__ void __launch_bounds__(256) gemm_tf32(
    const float* __restrict__ A, const float* __restrict__ B,
    const float* __restrict__ bias, float* __restrict__ C,
    int M, int N, int K, int klen)
{
    constexpr int ASTR = 36;
    constexpr int BSTR = BN + 8;
    constexpr int ACH  = BM / 32;
    constexpr int BCH  = BN / 32;
    constexpr int STG  = 3;

    __shared__ __align__(16) float As[STG][BM][ASTR];
    __shared__ __align__(16) float Bs[STG][32][BSTR];

    const int tid  = threadIdx.x;
    const int lane = tid & 31;
    const int warp = tid >> 5;
    const int wm   = warp >> 1;
    const int wn   = warp & 1;
    const int gid  = lane >> 2;
    const int tig  = lane & 3;

    const int bm = blockIdx.y * BM;
    const int bn = blockIdx.x * BN;
    const int kb = SPLIT ? blockIdx.z * klen : 0;
    if (SPLIT) C += (size_t)blockIdx.z * M * N;
    const int m_warp = wm * (MI * 16);
    const int n_warp = wn * (NI * 8);

    auto issue_tile = [&](int t, int stg) {
        const int k0 = kb + t * 32;
#pragma unroll
        for (int i = 0; i < ACH; i++) {
            int id  = tid + 256 * i;
            int row = id >> 3;
            int c4  = (id & 7) * 4;
            cp_async16(&As[stg][row][c4], A + (size_t)(bm + row) * K + k0 + c4);
        }
#pragma unroll
        for (int i = 0; i < BCH; i++) {
            int id  = tid + 256 * i;
            int rw  = id / (BN / 4);
            int c   = (id % (BN / 4)) * 4;
            int col = bn + c;
            const float* src = B + (size_t)(k0 + rw) * N + (col < N ? col : 0);
            cp_async16z(&Bs[stg][rw][c], src, col < N ? 16 : 0);
        }
    };

    float acc[MI][NI][4];
#pragma unroll
    for (int mi = 0; mi < MI; mi++)
#pragma unroll
        for (int ni = 0; ni < NI; ni++)
#pragma unroll
            for (int j = 0; j < 4; j++) acc[mi][ni][j] = 0.f;

    const int ktiles = (SPLIT ? klen : K) / 32;

#pragma unroll
    for (int t = 0; t < 2; t++) {
        if (t < ktiles) issue_tile(t, t);
        CP_COMMIT();
    }

    for (int t = 0; t < ktiles; t++) {
        CP_WAIT1();
        __syncthreads();

        if (t + 2 < ktiles) issue_tile(t + 2, (t + 2) % STG);
        CP_COMMIT();

        const int st = t % STG;
#pragma unroll
        for (int s = 0; s < 4; s++) {
            uint32_t af[MI][4], bf[NI][2];
#pragma unroll
            for (int mi = 0; mi < MI; mi++) {
                int r0 = m_warp + mi * 16 + gid;
                int kk = s * 8 + tig;
                af[mi][0] = f2tf32(As[st][r0][kk]);
                af[mi][1] = f2tf32(As[st][r0 + 8][kk]);
                af[mi][2] = f2tf32(As[st][r0][kk + 4]);
                af[mi][3] = f2tf32(As[st][r0 + 8][kk + 4]);
            }
#pragma unroll
            for (int ni = 0; ni < NI; ni++) {
                int n0 = n_warp + ni * 8 + gid;
                int kk = s * 8 + tig;
                bf[ni][0] = f2tf32(Bs[st][kk][n0]);
                bf[ni][1] = f2tf32(Bs[st][kk + 4][n0]);
            }
#pragma unroll
            for (int mi = 0; mi < MI; mi++)
#pragma unroll
                for (int ni = 0; ni < NI; ni++)
                    mma_tf32(acc[mi][ni], af[mi][0], af[mi][1], af[mi][2], af[mi][3],
                             bf[ni][0], bf[ni][1]);
        }
    }

    // epilogue
#pragma unroll
    for (int mi = 0; mi < MI; mi++) {
#pragma unroll
        for (int ni = 0; ni < NI; ni++) {
            int row = bm + m_warp + mi * 16 + gid;
            int col = bn + n_warp + ni * 8 + tig * 2;
            if (col < N) {
                float bx = 0.f, by = 0.f;
                if (!SPLIT && bias) { bx = bias[col]; by = bias[col + 1]; }
                float2 o0 = make_float2(acc[mi][ni][0] + bx, acc[mi][ni][1] + by);
                float2 o1 = make_float2(acc[mi][ni][2] + bx, acc[mi][ni][3] + by);
                *(float2*)(C + (size_t)row * N + col)       = o0;
                *(float2*)(C + (size_t)(row + 8) * N + col) = o1;
            }
        }
    }
}

// ---------------- fused split-K reduce + bias + rmsnorm (+ optional silu), N=1024 ----------------
template <bool DO_SILU>
__global__ void __launch_bounds__(256) reduce_rmsnorm_kernel(
    const float* __restrict__ P, const float* __restrict__ bias,
    const float* __restrict__ g, float* __restrict__ out)
{
    const int row = blockIdx.x;
    const int tid = threadIdx.x;
    const size_t stride = (size_t)BATCH * MAMBA_DIM;

    float4 v = ((const float4*)(P + (size_t)row * 1024))[tid];
#pragma unroll
    for (int s = 1; s < SPLITS; s++) {
        float4 t = ((const float4*)(P + s * stride + (size_t)row * 1024))[tid];
        v.x += t.x; v.y += t.y; v.z += t.z; v.w += t.w;
    }
    float4 bv = ((const float4*)bias)[tid];
    v.x += bv.x; v.y += bv.y; v.z += bv.z; v.w += bv.w;

    float ss = v.x * v.x + v.y * v.y + v.z * v.z + v.w * v.w;
    const int lane = tid & 31, warp = tid >> 5;
    __shared__ float red[8];
#pragma unroll
    for (int o = 16; o; o >>= 1) ss += __shfl_xor_sync(~0u, ss, o);
    if (lane == 0) red[warp] = ss;
    __syncthreads();
    if (warp == 0) {
        float t = (lane < 8) ? red[lane] : 0.f;
#pragma unroll
        for (int o = 4; o; o >>= 1) t += __shfl_xor_sync(~0u, t, o);
        if (lane == 0) red[0] = t;
    }
    __syncthreads();
    float scale = rsqrtf(red[0] * (1.f / 1024.f) + EPS);

    float4 gv = ((const float4*)g)[tid];
    float4 o;
    o.x = v.x * scale * gv.x;
    o.y = v.y * scale * gv.y;
    o.z = v.z * scale * gv.z;
    o.w = v.w * scale * gv.w;
    if (DO_SILU) {
        o.x = siluf(o.x); o.y = siluf(o.y); o.z = siluf(o.z); o.w = siluf(o.w);
    }
    ((float4*)(out + (size_t)row * 1024))[tid] = o;
}

// ---------------- plain split-K reduce (no bias) ----------------
__global__ void __launch_bounds__(256) reduce4_kernel(
    const float* __restrict__ P, float* __restrict__ out)
{
    const size_t i = (size_t)blockIdx.x * blockDim.x + threadIdx.x;   // float4 idx
    const size_t stride4 = (size_t)BATCH * MAMBA_DIM / 4;
    float4 v = ((const float4*)P)[i];
#pragma unroll
    for (int s = 1; s < SPLITS; s++) {
        float4 t = ((const float4*)P)[i + s * stride4];
        v.x += t.x; v.y += t.y; v.z += t.z; v.w += t.w;
    }
    ((float4*)out)[i] = v;
}

// ---------------- B/C conv (once per batch, no redundancy) ----------------
__global__ void __launch_bounds__(256) conv_bc_kernel(
    const float* __restrict__ conv_state, const float* __restrict__ zx,
    const float* __restrict__ conv_w, const float* __restrict__ conv_b,
    float* __restrict__ out_conv, float* __restrict__ bc)
{
    const int b  = blockIdx.x;
    const int t  = threadIdx.x;
    const int ch = D_INNER + t;
    const size_t cidx = (size_t)b * CONV_DIM + ch;

    float4 s  = ((const float4*)conv_state)[cidx];
    float  xn = zx[(size_t)b * D_IN_PROJ + D_INNER + ch];
    float4 ns = make_float4(s.y, s.z, s.w, xn);
    ((float4*)out_conv)[cidx] = ns;

    float4 w = ((const float4*)conv_w)[ch];
    float v = ns.x * w.x + ns.y * w.y + ns.z * w.z + ns.w * w.w + conv_b[ch];
    bc[b * BC_DIM + t] = siluf(v);
}

// ---------------- fused xh-conv + SSM update ----------------
// one block per (b,h); 8 warps; warp w owns p rows w*8..w*8+7.
// Loads batched 4-wide, compute/store split 2+2 to shape register lifetimes;
// 7 CTAs/SM forced (reg cap 36) -> 56 resident warps.
__global__ void __launch_bounds__(256, 7) ssm_kernel(
    const float* __restrict__ ssm_state, const float* __restrict__ zx,
    const float* __restrict__ conv_state, const float* __restrict__ conv_w,
    const float* __restrict__ conv_b, const float* __restrict__ bc,
    const float* __restrict__ A_log, const float* __restrict__ dt_bias,
    const float* __restrict__ Dvec,
    float* __restrict__ out_ssm, float* __restrict__ out_conv,
    float* __restrict__ ybuf)
{
    const int bh = blockIdx.x;
    const int b  = bh >> 5;
    const int h  = bh & 31;
    const int tid  = threadIdx.x;
    const int lane = tid & 31;
    const int warp = tid >> 5;

    const float* zxr = zx + (size_t)b * D_IN_PROJ;

    float dtraw = zxr[D_INNER + CONV_DIM + h] + dt_bias[h];
    float dtv = (dtraw > 20.f) ? dtraw : log1pf(expf(dtraw));
    float da  = expf(-expf(A_log[h]) * dtv);
    float Dh  = Dvec[h];

    __shared__ __align__(16) float sh_db[D_STATE];
    __shared__ __align__(16) float sh_c [D_STATE];
    __shared__ float sh_xh[HEADDIM];

    if (tid < 128) {
        sh_db[tid] = dtv * bc[b * BC_DIM + tid];
        sh_c [tid] = bc[b * BC_DIM + D_STATE + tid];
    } else if (tid < 192) {
        int p  = tid - 128;
        int ch = h * HEADDIM + p;
        size_t cidx = (size_t)b * CONV_DIM + ch;
        float4 s  = ((const float4*)conv_state)[cidx];
        float  xn = zxr[D_INNER + ch];
        float4 ns4 = make_float4(s.y, s.z, s.w, xn);
        ((float4*)out_conv)[cidx] = ns4;
        float4 w = ((const float4*)conv_w)[ch];
        float v = ns4.x * w.x + ns4.y * w.y + ns4.z * w.z + ns4.w * w.w + conv_b[ch];
        sh_xh[p] = siluf(v);
    }
    __syncthreads();

    const size_t base4 = (size_t)bh * HEADDIM * (D_STATE / 4);
    const float4* ss4 = (const float4*)ssm_state + base4;
    float4*       os4 = (float4*)out_ssm + base4;

    float4 c4  = ((const float4*)sh_c)[lane];
    float4 db4 = ((const float4*)sh_db)[lane];

#pragma unroll
    for (int half = 0; half < 2; half++) {
        const int p0 = warp * 8 + half * 4;

        // 4-wide load burst (MLP=4 at issue)
        float4 sv[4];
#pragma unroll
        for (int i = 0; i < 4; i++)
            sv[i] = __ldcs(&ss4[(p0 + i) * 32 + lane]);

        // consume in two 2-row groups: sv[i] dies as ns is produced
#pragma unroll
        for (int g2 = 0; g2 < 2; g2++) {
#pragma unroll
            for (int i = g2 * 2; i < g2 * 2 + 2; i++) {
                int p = p0 + i;
                float xv = sh_xh[p];
                float4 ns;
                ns.x = fmaf(sv[i].x, da, xv * db4.x);
                ns.y = fmaf(sv[i].y, da, xv * db4.y);
                ns.z = fmaf(sv[i].z, da, xv * db4.z);
                ns.w = fmaf(sv[i].w, da, xv * db4.w);
                __stcs(&os4[p * 32 + lane], ns);

                float part = ns.x * c4.x + ns.y * c4.y + ns.z * c4.z + ns.w * c4.w;
#pragma unroll
                for (int o = 16; o; o >>= 1) part += __shfl_xor_sync(~0u, part, o);
                if (lane == 0) {
                    float yv = part + Dh * xv;
                    float z  = zxr[h * HEADDIM + p];
                    ybuf[(size_t)b * D_INNER + h * HEADDIM + p] = yv * siluf(z);
                }
            }
        }
    }
}

// ---------------- launch ----------------
extern "C" void kernel_launch(void* const* d_in, const int* in_sizes, int n_in,
                              void* d_out, int out_size)
{
    const float* x          = (const float*)d_in[0];
    const float* conv_state = (const float*)d_in[1];
    const float* ssm_state  = (const float*)d_in[2];
    const float* w_in       = (const float*)d_in[3];
    const float* b_in       = (const float*)d_in[4];
    const float* g_in       = (const float*)d_in[5];
    const float* W_inproj   = (const float*)d_in[6];
    const float* conv_w     = (const float*)d_in[7];
    const float* conv_b     = (const float*)d_in[8];
    const float* A_log      = (const float*)d_in[9];
    const float* dt_bias    = (const float*)d_in[10];
    const float* Dvec       = (const float*)d_in[11];
    const float* W_mamba    = (const float*)d_in[12];
    const float* w_out      = (const float*)d_in[13];
    const float* b_out      = (const float*)d_in[14];
    const float* g_outnorm  = (const float*)d_in[15];

    float* out      = (float*)d_out;
    float* out_y    = out + OUT_Y_OFF;
    float* out_conv = out + OUT_CONV_OFF;
    float* out_ssm  = out + OUT_SSM_OFF;

    float *h, *zx, *bc, *ybuf, *t2, *part;
    cudaGetSymbolAddress((void**)&h,    g_h);
    cudaGetSymbolAddress((void**)&zx,   g_zx);
    cudaGetSymbolAddress((void**)&bc,   g_bc);
    cudaGetSymbolAddress((void**)&ybuf, g_ybuf);
    cudaGetSymbolAddress((void**)&t2,   g_t2);
    cudaGetSymbolAddress((void**)&part, g_part);

    // 1) split-K: part[s] = x @ w_in (slice s)   [512,1536]x[1536,1024]
    gemm_tf32<128, 128, 2, 8, true><<<dim3(8, 4, SPLITS), 256>>>(
        x, w_in, nullptr, part, BATCH, MAMBA_DIM, INPUT_DIM, INPUT_DIM / SPLITS);
    // 2) h = silu(rmsnorm(sum(part) + b_in, g_in))
    reduce_rmsnorm_kernel<true><<<BATCH, 256>>>(part, b_in, g_in, h);
    // 3) zx = h @ W_inproj        [512,1024]x[1024,4384]  (140 blocks)
    gemm_tf32<128, 128, 2, 8, false><<<dim3((D_IN_PROJ + 127) / 128, BATCH / 128), 256>>>(
        h, W_inproj, nullptr, zx, BATCH, D_IN_PROJ, MAMBA_DIM, MAMBA_DIM);
    // 4) B/C conv once per batch (writes bc + its slice of out_conv)
    conv_bc_kernel<<<BATCH, 256>>>(conv_state, zx, conv_w, conv_b, out_conv, bc);
    // 5) fused xh-conv + SSM update (writes out_conv xh slice, out_ssm, ybuf)
    ssm_kernel<<<BATCH * NHEADS, 256>>>(
        ssm_state, zx, conv_state, conv_w, conv_b, bc,
        A_log, dt_bias, Dvec, out_ssm, out_conv, ybuf);
    // 6) split-K: part[s] = ybuf @ W_mamba_out (slice s)  [512,2048]x[2048,1024]
    gemm_tf32<128, 128, 2, 8, true><<<dim3(8, 4, SPLITS), 256>>>(
        ybuf, W_mamba, nullptr, part, BATCH, MAMBA_DIM, D_INNER, D_INNER / SPLITS);
    // 7) t2 = sum(part)
    reduce4_kernel<<<BATCH, 256>>>(part, t2);
    // 8) split-K: part[s] = t2 @ w_out (slice s)  [512,1024]x[1024,1024]
    gemm_tf32<128, 128, 2, 8, true><<<dim3(8, 4, SPLITS), 256>>>(
        t2, w_out, nullptr, part, BATCH, OUTPUT_DIM, MAMBA_DIM, MAMBA_DIM / SPLITS);
    // 9) out_y = rmsnorm(sum(part) + b_out, g_outnorm)
    reduce_rmsnorm_kernel<false><<<BATCH, 256>>>(part, b_out, g_outnorm, out_y);
}

// round 13
// speedup vs baseline: 1.0788x; 1.0788x over previous
#include <cuda_runtime.h>
#include <cuda_bf16.h>
#include <math.h>
#include <stdint.h>

// ---------------- problem constants ----------------
#define BATCH      512
#define INPUT_DIM  1536
#define MAMBA_DIM  1024
#define OUTPUT_DIM 1024
#define D_STATE    128
#define D_CONV     4
#define HEADDIM    64
#define D_INNER    2048
#define NHEADS     32
#define CONV_DIM   2304          // D_INNER + 2*D_STATE
#define D_IN_PROJ  4384          // 2*D_INNER + 2*D_STATE + NHEADS
#define EPS        1e-5f
#define SPLITS     4
#define BC_DIM     (2 * D_STATE)             // 256

// output regions (floats)
#define OUT_Y_OFF    0
#define OUT_CONV_OFF (BATCH * OUTPUT_DIM)                       // 524288
#define OUT_SSM_OFF  (OUT_CONV_OFF + BATCH * CONV_DIM * D_CONV) // 5242880

// ---------------- scratch (global device arrays, no allocation) ----------------
__device__ float g_h   [BATCH * MAMBA_DIM];            // silu(rmsnorm(...))
__device__ float g_zx  [BATCH * D_IN_PROJ];            // zxbcdt
__device__ float g_bc  [BATCH * BC_DIM];               // silu(conv) of B/C channels
__device__ float g_ybuf[BATCH * D_INNER];              // gated y before out proj
__device__ float g_t2  [BATCH * MAMBA_DIM];            // y@W_mamba_out
__device__ float g_part[SPLITS * BATCH * MAMBA_DIM];   // split-K partials (8MB)

// ---------------- helpers ----------------
__device__ __forceinline__ float siluf(float v) { return v / (1.f + expf(-v)); }

__device__ __forceinline__ uint32_t f2tf32(float f) {
    uint32_t u;
    asm("cvt.rna.tf32.f32 %0, %1;" : "=r"(u) : "f"(f));
    return u;
}

__device__ __forceinline__ void mma_tf32(float* c,
                                         uint32_t a0, uint32_t a1, uint32_t a2, uint32_t a3,
                                         uint32_t b0, uint32_t b1) {
    asm volatile(
        "mma.sync.aligned.m16n8k8.row.col.f32.tf32.tf32.f32 "
        "{%0,%1,%2,%3}, {%4,%5,%6,%7}, {%8,%9}, {%0,%1,%2,%3};"
        : "+f"(c[0]), "+f"(c[1]), "+f"(c[2]), "+f"(c[3])
        : "r"(a0), "r"(a1), "r"(a2), "r"(a3), "r"(b0), "r"(b1));
}

__device__ __forceinline__ void cp_async16(void* smem_dst, const void* gsrc) {
    uint32_t d = (uint32_t)__cvta_generic_to_shared(smem_dst);
    asm volatile("cp.async.cg.shared.global [%0], [%1], 16;\n" :: "r"(d), "l"(gsrc));
}
__device__ __forceinline__ void cp_async16z(void* smem_dst, const void* gsrc, int src_bytes) {
    uint32_t d = (uint32_t)__cvta_generic_to_shared(smem_dst);
    asm volatile("cp.async.cg.shared.global [%0], [%1], 16, %2;\n"
                 :: "r"(d), "l"(gsrc), "r"(src_bytes));
}
#define CP_COMMIT() asm volatile("cp.async.commit_group;\n" ::: "memory")
#define CP_WAIT1()  asm volatile("cp.async.wait_group 1;\n" ::: "memory")

// ---------------- TF32 tensor-core GEMM, 3-stage cp.async pipeline (round-9 proven) ----------------
template <int BM, int BN, int MI, int NI, bool SPLIT>
__global__ void __launch_bounds__(256) gemm_tf32(
    const float* __restrict__ A, const float* __restrict__ B,
    const float* __restrict__ bias, float* __restrict__ C,
    int M, int N, int K, int klen)
{
    constexpr int ASTR = 36;
    constexpr int BSTR = BN + 8;
    constexpr int ACH  = BM / 32;
    constexpr int BCH  = BN / 32;
    constexpr int STG  = 3;

    __shared__ __align__(16) float As[STG][BM][ASTR];
    __shared__ __align__(16) float Bs[STG][32][BSTR];

    const int tid  = threadIdx.x;
    const int lane = tid & 31;
    const int warp = tid >> 5;
    const int wm   = warp >> 1;
    const int wn   = warp & 1;
    const int gid  = lane >> 2;
    const int tig  = lane & 3;

    const int bm = blockIdx.y * BM;
    const int bn = blockIdx.x * BN;
    const int kb = SPLIT ? blockIdx.z * klen : 0;
    if (SPLIT) C += (size_t)blockIdx.z * M * N;
    const int m_warp = wm * (MI * 16);
    const int n_warp = wn * (NI * 8);

    auto issue_tile = [&](int t, int stg) {
        const int k0 = kb + t * 32;
#pragma unroll
        for (int i = 0; i < ACH; i++) {
            int id  = tid + 256 * i;
            int row = id >> 3;
            int c4  = (id & 7) * 4;
            cp_async16(&As[stg][row][c4], A + (size_t)(bm + row) * K + k0 + c4);
        }
#pragma unroll
        for (int i = 0; i < BCH; i++) {
            int id  = tid + 256 * i;
            int rw  = id / (BN / 4);
            int c   = (id % (BN / 4)) * 4;
            int col = bn + c;
            const float* src = B + (size_t)(k0 + rw) * N + (col < N ? col : 0);
            cp_async16z(&Bs[stg][rw][c], src, col < N ? 16 : 0);
        }
    };

    float acc[MI][NI][4];
#pragma unroll
    for (int mi = 0; mi < MI; mi++)
#pragma unroll
        for (int ni = 0; ni < NI; ni++)
#pragma unroll
            for (int j = 0; j < 4; j++) acc[mi][ni][j] = 0.f;

    const int ktiles = (SPLIT ? klen : K) / 32;

#pragma unroll
    for (int t = 0; t < 2; t++) {
        if (t < ktiles) issue_tile(t, t);
        CP_COMMIT();
    }

    for (int t = 0; t < ktiles; t++) {
        CP_WAIT1();
        __syncthreads();

        if (t + 2 < ktiles) issue_tile(t + 2, (t + 2) % STG);
        CP_COMMIT();

        const int st = t % STG;
#pragma unroll
        for (int s = 0; s < 4; s++) {
            uint32_t af[MI][4], bf[NI][2];
#pragma unroll
            for (int mi = 0; mi < MI; mi++) {
                int r0 = m_warp + mi * 16 + gid;
                int kk = s * 8 + tig;
                af[mi][0] = f2tf32(As[st][r0][kk]);
                af[mi][1] = f2tf32(As[st][r0 + 8][kk]);
                af[mi][2] = f2tf32(As[st][r0][kk + 4]);
                af[mi][3] = f2tf32(As[st][r0 + 8][kk + 4]);
            }
#pragma unroll
            for (int ni = 0; ni < NI; ni++) {
                int n0 = n_warp + ni * 8 + gid;
                int kk = s * 8 + tig;
                bf[ni][0] = f2tf32(Bs[st][kk][n0]);
                bf[ni][1] = f2tf32(Bs[st][kk + 4][n0]);
            }
#pragma unroll
            for (int mi = 0; mi < MI; mi++)
#pragma unroll
                for (int ni = 0; ni < NI; ni++)
                    mma_tf32(acc[mi][ni], af[mi][0], af[mi][1], af[mi][2], af[mi][3],
                             bf[ni][0], bf[ni][1]);
        }
    }

    // epilogue
#pragma unroll
    for (int mi = 0; mi < MI; mi++) {
#pragma unroll
        for (int ni = 0; ni < NI; ni++) {
            int row = bm + m_warp + mi * 16 + gid;
            int col = bn + n_warp + ni * 8 + tig * 2;
            if (col < N) {
                float bx = 0.f, by = 0.f;
                if (!SPLIT && bias) { bx = bias[col]; by = bias[col + 1]; }
                float2 o0 = make_float2(acc[mi][ni][0] + bx, acc[mi][ni][1] + by);
                float2 o1 = make_float2(acc[mi][ni][2] + bx, acc[mi][ni][3] + by);
                *(float2*)(C + (size_t)row * N + col)       = o0;
                *(float2*)(C + (size_t)(row + 8) * N + col) = o1;
            }
        }
    }
}

// ---------------- fused split-K reduce + bias + rmsnorm (+ optional silu), N=1024 ----------------
template <bool DO_SILU>
__global__ void __launch_bounds__(256) reduce_rmsnorm_kernel(
    const float* __restrict__ P, const float* __restrict__ bias,
    const float* __restrict__ g, float* __restrict__ out)
{
    const int row = blockIdx.x;
    const int tid = threadIdx.x;
    const size_t stride = (size_t)BATCH * MAMBA_DIM;

    float4 v = ((const float4*)(P + (size_t)row * 1024))[tid];
#pragma unroll
    for (int s = 1; s < SPLITS; s++) {
        float4 t = ((const float4*)(P + s * stride + (size_t)row * 1024))[tid];
        v.x += t.x; v.y += t.y; v.z += t.z; v.w += t.w;
    }
    float4 bv = ((const float4*)bias)[tid];
    v.x += bv.x; v.y += bv.y; v.z += bv.z; v.w += bv.w;

    float ss = v.x * v.x + v.y * v.y + v.z * v.z + v.w * v.w;
    const int lane = tid & 31, warp = tid >> 5;
    __shared__ float red[8];
#pragma unroll
    for (int o = 16; o; o >>= 1) ss += __shfl_xor_sync(~0u, ss, o);
    if (lane == 0) red[warp] = ss;
    __syncthreads();
    if (warp == 0) {
        float t = (lane < 8) ? red[lane] : 0.f;
#pragma unroll
        for (int o = 4; o; o >>= 1) t += __shfl_xor_sync(~0u, t, o);
        if (lane == 0) red[0] = t;
    }
    __syncthreads();
    float scale = rsqrtf(red[0] * (1.f / 1024.f) + EPS);

    float4 gv = ((const float4*)g)[tid];
    float4 o;
    o.x = v.x * scale * gv.x;
    o.y = v.y * scale * gv.y;
    o.z = v.z * scale * gv.z;
    o.w = v.w * scale * gv.w;
    if (DO_SILU) {
        o.x = siluf(o.x); o.y = siluf(o.y); o.z = siluf(o.z); o.w = siluf(o.w);
    }
    ((float4*)(out + (size_t)row * 1024))[tid] = o;
}

// ---------------- plain split-K reduce (no bias) ----------------
__global__ void __launch_bounds__(256) reduce4_kernel(
    const float* __restrict__ P, float* __restrict__ out)
{
    const size_t i = (size_t)blockIdx.x * blockDim.x + threadIdx.x;   // float4 idx
    const size_t stride4 = (size_t)BATCH * MAMBA_DIM / 4;
    float4 v = ((const float4*)P)[i];
#pragma unroll
    for (int s = 1; s < SPLITS; s++) {
        float4 t = ((const float4*)P)[i + s * stride4];
        v.x += t.x; v.y += t.y; v.z += t.z; v.w += t.w;
    }
    ((float4*)out)[i] = v;
}

// ---------------- B/C conv (once per batch, no redundancy) ----------------
__global__ void __launch_bounds__(256) conv_bc_kernel(
    const float* __restrict__ conv_state, const float* __restrict__ zx,
    const float* __restrict__ conv_w, const float* __restrict__ conv_b,
    float* __restrict__ out_conv, float* __restrict__ bc)
{
    const int b  = blockIdx.x;
    const int t  = threadIdx.x;
    const int ch = D_INNER + t;
    const size_t cidx = (size_t)b * CONV_DIM + ch;

    float4 s  = ((const float4*)conv_state)[cidx];
    float  xn = zx[(size_t)b * D_IN_PROJ + D_INNER + ch];
    float4 ns = make_float4(s.y, s.z, s.w, xn);
    ((float4*)out_conv)[cidx] = ns;

    float4 w = ((const float4*)conv_w)[ch];
    float v = ns.x * w.x + ns.y * w.y + ns.z * w.z + ns.w * w.w + conv_b[ch];
    bc[b * BC_DIM + t] = siluf(v);
}

// ---------------- fused xh-conv + SSM update (round-11 optimum) ----------------
// one block per (b,h); 8 warps; warp w owns p rows w*8..w*8+7 in two batches of 4.
// 6 CTAs/SM (reg cap 42) — empirically the reg/occupancy optimum (r10/r11/r12).
__global__ void __launch_bounds__(256, 6) ssm_kernel(
    const float* __restrict__ ssm_state, const float* __restrict__ zx,
    const float* __restrict__ conv_state, const float* __restrict__ conv_w,
    const float* __restrict__ conv_b, const float* __restrict__ bc,
    const float* __restrict__ A_log, const float* __restrict__ dt_bias,
    const float* __restrict__ Dvec,
    float* __restrict__ out_ssm, float* __restrict__ out_conv,
    float* __restrict__ ybuf)
{
    const int bh = blockIdx.x;
    const int b  = bh >> 5;
    const int h  = bh & 31;
    const int tid  = threadIdx.x;
    const int lane = tid & 31;
    const int warp = tid >> 5;

    const float* zxr = zx + (size_t)b * D_IN_PROJ;

    float dtraw = zxr[D_INNER + CONV_DIM + h] + dt_bias[h];
    float dtv = (dtraw > 20.f) ? dtraw : log1pf(expf(dtraw));
    float da  = expf(-expf(A_log[h]) * dtv);
    float Dh  = Dvec[h];

    __shared__ __align__(16) float sh_db[D_STATE];
    __shared__ __align__(16) float sh_c [D_STATE];
    __shared__ float sh_xh[HEADDIM];

    if (tid < 128) {
        sh_db[tid] = dtv * bc[b * BC_DIM + tid];
        sh_c [tid] = bc[b * BC_DIM + D_STATE + tid];
    } else if (tid < 192) {
        int p  = tid - 128;
        int ch = h * HEADDIM + p;
        size_t cidx = (size_t)b * CONV_DIM + ch;
        float4 s  = ((const float4*)conv_state)[cidx];
        float  xn = zxr[D_INNER + ch];
        float4 ns4 = make_float4(s.y, s.z, s.w, xn);
        ((float4*)out_conv)[cidx] = ns4;
        float4 w = ((const float4*)conv_w)[ch];
        float v = ns4.x * w.x + ns4.y * w.y + ns4.z * w.z + ns4.w * w.w + conv_b[ch];
        sh_xh[p] = siluf(v);
    }
    __syncthreads();

    const size_t base4 = (size_t)bh * HEADDIM * (D_STATE / 4);
    const float4* ss4 = (const float4*)ssm_state + base4;
    float4*       os4 = (float4*)out_ssm + base4;

    float4 c4  = ((const float4*)sh_c)[lane];
    float4 db4 = ((const float4*)sh_db)[lane];

#pragma unroll
    for (int half = 0; half < 2; half++) {
        const int p0 = warp * 8 + half * 4;

        float4 sv[4];
#pragma unroll
        for (int i = 0; i < 4; i++)
            sv[i] = __ldcs(&ss4[(p0 + i) * 32 + lane]);

#pragma unroll
        for (int i = 0; i < 4; i++) {
            int p = p0 + i;
            float xv = sh_xh[p];
            float4 ns;
            ns.x = fmaf(sv[i].x, da, xv * db4.x);
            ns.y = fmaf(sv[i].y, da, xv * db4.y);
            ns.z = fmaf(sv[i].z, da, xv * db4.z);
            ns.w = fmaf(sv[i].w, da, xv * db4.w);
            __stcs(&os4[p * 32 + lane], ns);

            float part = ns.x * c4.x + ns.y * c4.y + ns.z * c4.z + ns.w * c4.w;
#pragma unroll
            for (int o = 16; o; o >>= 1) part += __shfl_xor_sync(~0u, part, o);
            if (lane == 0) {
                float yv = part + Dh * xv;
                float z  = zxr[h * HEADDIM + p];
                ybuf[(size_t)b * D_INNER + h * HEADDIM + p] = yv * siluf(z);
            }
        }
    }
}

// ---------------- launch ----------------
extern "C" void kernel_launch(void* const* d_in, const int* in_sizes, int n_in,
                              void* d_out, int out_size)
{
    const float* x          = (const float*)d_in[0];
    const float* conv_state = (const float*)d_in[1];
    const float* ssm_state  = (const float*)d_in[2];
    const float* w_in       = (const float*)d_in[3];
    const float* b_in       = (const float*)d_in[4];
    const float* g_in       = (const float*)d_in[5];
    const float* W_inproj   = (const float*)d_in[6];
    const float* conv_w     = (const float*)d_in[7];
    const float* conv_b     = (const float*)d_in[8];
    const float* A_log      = (const float*)d_in[9];
    const float* dt_bias    = (const float*)d_in[10];
    const float* Dvec       = (const float*)d_in[11];
    const float* W_mamba    = (const float*)d_in[12];
    const float* w_out      = (const float*)d_in[13];
    const float* b_out      = (const float*)d_in[14];
    const float* g_outnorm  = (const float*)d_in[15];

    float* out      = (float*)d_out;
    float* out_y    = out + OUT_Y_OFF;
    float* out_conv = out + OUT_CONV_OFF;
    float* out_ssm  = out + OUT_SSM_OFF;

    float *h, *zx, *bc, *ybuf, *t2, *part;
    cudaGetSymbolAddress((void**)&h,    g_h);
    cudaGetSymbolAddress((void**)&zx,   g_zx);
    cudaGetSymbolAddress((void**)&bc,   g_bc);
    cudaGetSymbolAddress((void**)&ybuf, g_ybuf);
    cudaGetSymbolAddress((void**)&t2,   g_t2);
    cudaGetSymbolAddress((void**)&part, g_part);

    // 1) split-K: part[s] = x @ w_in (slice s)   [512,1536]x[1536,1024]
    gemm_tf32<128, 128, 2, 8, true><<<dim3(8, 4, SPLITS), 256>>>(
        x, w_in, nullptr, part, BATCH, MAMBA_DIM, INPUT_DIM, INPUT_DIM / SPLITS);
    // 2) h = silu(rmsnorm(sum(part) + b_in, g_in))
    reduce_rmsnorm_kernel<true><<<BATCH, 256>>>(part, b_in, g_in, h);
    // 3) zx = h @ W_inproj        [512,1024]x[1024,4384]  (140 blocks)
    gemm_tf32<128, 128, 2, 8, false><<<dim3((D_IN_PROJ + 127) / 128, BATCH / 128), 256>>>(
        h, W_inproj, nullptr, zx, BATCH, D_IN_PROJ, MAMBA_DIM, MAMBA_DIM);
    // 4) B/C conv once per batch (writes bc + its slice of out_conv)
    conv_bc_kernel<<<BATCH, 256>>>(conv_state, zx, conv_w, conv_b, out_conv, bc);
    // 5) fused xh-conv + SSM update (writes out_conv xh slice, out_ssm, ybuf)
    ssm_kernel<<<BATCH * NHEADS, 256>>>(
        ssm_state, zx, conv_state, conv_w, conv_b, bc,
        A_log, dt_bias, Dvec, out_ssm, out_conv, ybuf);
    // 6) split-K: part[s] = ybuf @ W_mamba_out (slice s)  [512,2048]x[2048,1024]
    gemm_tf32<128, 128, 2, 8, true><<<dim3(8, 4, SPLITS), 256>>>(
        ybuf, W_mamba, nullptr, part, BATCH, MAMBA_DIM, D_INNER, D_INNER / SPLITS);
    // 7) t2 = sum(part)
    reduce4_kernel<<<BATCH, 256>>>(part, t2);
    // 8) split-K: part[s] = t2 @ w_out (slice s)  [512,1024]x[1024,1024]
    gemm_tf32<128, 128, 2, 8, true><<<dim3(8, 4, SPLITS), 256>>>(
        t2, w_out, nullptr, part, BATCH, OUTPUT_DIM, MAMBA_DIM, MAMBA_DIM / SPLITS);
    // 9) out_y = rmsnorm(sum(part) + b_out, g_outnorm)
    reduce_rmsnorm_kernel<false><<<BATCH, 256>>>(part, b_out, g_outnorm, out_y);
}

// round 14
// speedup vs baseline: 1.1007x; 1.0204x over previous
#include <cuda_runtime.h>
#include <cuda_bf16.h>
#include <math.h>
#include <stdint.h>

// ---------------- problem constants ----------------
#define BATCH      512
#define INPUT_DIM  1536
#define MAMBA_DIM  1024
#define OUTPUT_DIM 1024
#define D_STATE    128
#define D_CONV     4
#define HEADDIM    64
#define D_INNER    2048
#define NHEADS     32
#define CONV_DIM   2304          // D_INNER + 2*D_STATE
#define D_IN_PROJ  4384          // 2*D_INNER + 2*D_STATE + NHEADS
#define EPS        1e-5f
#define SPLITS     4
#define BC_DIM     (2 * D_STATE)             // 256

// output regions (floats)
#define OUT_Y_OFF    0
#define OUT_CONV_OFF (BATCH * OUTPUT_DIM)                       // 524288
#define OUT_SSM_OFF  (OUT_CONV_OFF + BATCH * CONV_DIM * D_CONV) // 5242880

// ---------------- PDL intrinsics (sm_90+) ----------------
#if defined(__CUDA_ARCH__) && (__CUDA_ARCH__ >= 900)
#define PDL_WAIT()    cudaGridDependencySynchronize()
#define PDL_TRIGGER() cudaTriggerProgrammaticLaunchCompletion()
#else
#define PDL_WAIT()
#define PDL_TRIGGER()
#endif

// ---------------- scratch (global device arrays, no allocation) ----------------
__device__ float g_h   [BATCH * MAMBA_DIM];            // silu(rmsnorm(...))
__device__ float g_zx  [BATCH * D_IN_PROJ];            // zxbcdt
__device__ float g_bc  [BATCH * BC_DIM];               // silu(conv) of B/C channels
__device__ float g_ybuf[BATCH * D_INNER];              // gated y before out proj
__device__ float g_t2  [BATCH * MAMBA_DIM];            // y@W_mamba_out
__device__ float g_part[SPLITS * BATCH * MAMBA_DIM];   // split-K partials (8MB)

// ---------------- helpers ----------------
__device__ __forceinline__ float siluf(float v) { return v / (1.f + expf(-v)); }

__device__ __forceinline__ uint32_t f2tf32(float f) {
    uint32_t u;
    asm("cvt.rna.tf32.f32 %0, %1;" : "=r"(u) : "f"(f));
    return u;
}

__device__ __forceinline__ void mma_tf32(float* c,
                                         uint32_t a0, uint32_t a1, uint32_t a2, uint32_t a3,
                                         uint32_t b0, uint32_t b1) {
    asm volatile(
        "mma.sync.aligned.m16n8k8.row.col.f32.tf32.tf32.f32 "
        "{%0,%1,%2,%3}, {%4,%5,%6,%7}, {%8,%9}, {%0,%1,%2,%3};"
        : "+f"(c[0]), "+f"(c[1]), "+f"(c[2]), "+f"(c[3])
        : "r"(a0), "r"(a1), "r"(a2), "r"(a3), "r"(b0), "r"(b1));
}

__device__ __forceinline__ void cp_async16(void* smem_dst, const void* gsrc) {
    uint32_t d = (uint32_t)__cvta_generic_to_shared(smem_dst);
    asm volatile("cp.async.cg.shared.global [%0], [%1], 16;\n" :: "r"(d), "l"(gsrc));
}
__device__ __forceinline__ void cp_async16z(void* smem_dst, const void* gsrc, int src_bytes) {
    uint32_t d = (uint32_t)__cvta_generic_to_shared(smem_dst);
    asm volatile("cp.async.cg.shared.global [%0], [%1], 16, %2;\n"
                 :: "r"(d), "l"(gsrc), "r"(src_bytes));
}
#define CP_COMMIT() asm volatile("cp.async.commit_group;\n" ::: "memory")
#define CP_WAIT1()  asm volatile("cp.async.wait_group 1;\n" ::: "memory")

// ---------------- TF32 tensor-core GEMM, 3-stage cp.async pipeline (round-9 proven) ----------------
template <int BM, int BN, int MI, int NI, bool SPLIT>
__global__ void __launch_bounds__(256) gemm_tf32(
    const float* __restrict__ A, const float* __restrict__ B,
    const float* __restrict__ bias, float* __restrict__ C,
    int M, int N, int K, int klen)
{
    constexpr int ASTR = 36;
    constexpr int BSTR = BN + 8;
    constexpr int ACH  = BM / 32;
    constexpr int BCH  = BN / 32;
    constexpr int STG  = 3;

    __shared__ __align__(16) float As[STG][BM][ASTR];
    __shared__ __align__(16) float Bs[STG][32][BSTR];

    const int tid  = threadIdx.x;
    const int lane = tid & 31;
    const int warp = tid >> 5;
    const int wm   = warp >> 1;
    const int wn   = warp & 1;
    const int gid  = lane >> 2;
    const int tig  = lane & 3;

    const int bm = blockIdx.y * BM;
    const int bn = blockIdx.x * BN;
    const int kb = SPLIT ? blockIdx.z * klen : 0;
    if (SPLIT) C += (size_t)blockIdx.z * M * N;
    const int m_warp = wm * (MI * 16);
    const int n_warp = wn * (NI * 8);

    auto issue_tile = [&](int t, int stg) {
        const int k0 = kb + t * 32;
#pragma unroll
        for (int i = 0; i < ACH; i++) {
            int id  = tid + 256 * i;
            int row = id >> 3;
            int c4  = (id & 7) * 4;
            cp_async16(&As[stg][row][c4], A + (size_t)(bm + row) * K + k0 + c4);
        }
#pragma unroll
        for (int i = 0; i < BCH; i++) {
            int id  = tid + 256 * i;
            int rw  = id / (BN / 4);
            int c   = (id % (BN / 4)) * 4;
            int col = bn + c;
            const float* src = B + (size_t)(k0 + rw) * N + (col < N ? col : 0);
            cp_async16z(&Bs[stg][rw][c], src, col < N ? 16 : 0);
        }
    };

    float acc[MI][NI][4];
#pragma unroll
    for (int mi = 0; mi < MI; mi++)
#pragma unroll
        for (int ni = 0; ni < NI; ni++)
#pragma unroll
            for (int j = 0; j < 4; j++) acc[mi][ni][j] = 0.f;

    const int ktiles = (SPLIT ? klen : K) / 32;

    // wait for producer's writes to be visible before first global read
    PDL_WAIT();

#pragma unroll
    for (int t = 0; t < 2; t++) {
        if (t < ktiles) issue_tile(t, t);
        CP_COMMIT();
    }

    for (int t = 0; t < ktiles; t++) {
        CP_WAIT1();
        __syncthreads();

        if (t + 2 < ktiles) issue_tile(t + 2, (t + 2) % STG);
        CP_COMMIT();

        const int st = t % STG;
#pragma unroll
        for (int s = 0; s < 4; s++) {
            uint32_t af[MI][4], bf[NI][2];
#pragma unroll
            for (int mi = 0; mi < MI; mi++) {
                int r0 = m_warp + mi * 16 + gid;
                int kk = s * 8 + tig;
                af[mi][0] = f2tf32(As[st][r0][kk]);
                af[mi][1] = f2tf32(As[st][r0 + 8][kk]);
                af[mi][2] = f2tf32(As[st][r0][kk + 4]);
                af[mi][3] = f2tf32(As[st][r0 + 8][kk + 4]);
            }
#pragma unroll
            for (int ni = 0; ni < NI; ni++) {
                int n0 = n_warp + ni * 8 + gid;
                int kk = s * 8 + tig;
                bf[ni][0] = f2tf32(Bs[st][kk][n0]);
                bf[ni][1] = f2tf32(Bs[st][kk + 4][n0]);
            }
#pragma unroll
            for (int mi = 0; mi < MI; mi++)
#pragma unroll
                for (int ni = 0; ni < NI; ni++)
                    mma_tf32(acc[mi][ni], af[mi][0], af[mi][1], af[mi][2], af[mi][3],
                             bf[ni][0], bf[ni][1]);
        }
    }

    // allow dependents to start launching while the epilogue drains
    PDL_TRIGGER();

    // epilogue
#pragma unroll
    for (int mi = 0; mi < MI; mi++) {
#pragma unroll
        for (int ni = 0; ni < NI; ni++) {
            int row = bm + m_warp + mi * 16 + gid;
            int col = bn + n_warp + ni * 8 + tig * 2;
            if (col < N) {
                float bx = 0.f, by = 0.f;
                if (!SPLIT && bias) { bx = bias[col]; by = bias[col + 1]; }
                float2 o0 = make_float2(acc[mi][ni][0] + bx, acc[mi][ni][1] + by);
                float2 o1 = make_float2(acc[mi][ni][2] + bx, acc[mi][ni][3] + by);
                *(float2*)(C + (size_t)row * N + col)       = o0;
                *(float2*)(C + (size_t)(row + 8) * N + col) = o1;
            }
        }
    }
}

// ---------------- fused split-K reduce + bias + rmsnorm (+ optional silu), N=1024 ----------------
template <bool DO_SILU>
__global__ void __launch_bounds__(256) reduce_rmsnorm_kernel(
    const float* __restrict__ P, const float* __restrict__ bias,
    const float* __restrict__ g, float* __restrict__ out)
{
    const int row = blockIdx.x;
    const int tid = threadIdx.x;
    const size_t stride = (size_t)BATCH * MAMBA_DIM;

    PDL_WAIT();

    float4 v = ((const float4*)(P + (size_t)row * 1024))[tid];
#pragma unroll
    for (int s = 1; s < SPLITS; s++) {
        float4 t = ((const float4*)(P + s * stride + (size_t)row * 1024))[tid];
        v.x += t.x; v.y += t.y; v.z += t.z; v.w += t.w;
    }
    float4 bv = ((const float4*)bias)[tid];
    v.x += bv.x; v.y += bv.y; v.z += bv.z; v.w += bv.w;

    float ss = v.x * v.x + v.y * v.y + v.z * v.z + v.w * v.w;
    const int lane = tid & 31, warp = tid >> 5;
    __shared__ float red[8];
#pragma unroll
    for (int o = 16; o; o >>= 1) ss += __shfl_xor_sync(~0u, ss, o);
    if (lane == 0) red[warp] = ss;
    __syncthreads();
    if (warp == 0) {
        float t = (lane < 8) ? red[lane] : 0.f;
#pragma unroll
        for (int o = 4; o; o >>= 1) t += __shfl_xor_sync(~0u, t, o);
        if (lane == 0) red[0] = t;
    }
    __syncthreads();
    float scale = rsqrtf(red[0] * (1.f / 1024.f) + EPS);

    float4 gv = ((const float4*)g)[tid];
    float4 o;
    o.x = v.x * scale * gv.x;
    o.y = v.y * scale * gv.y;
    o.z = v.z * scale * gv.z;
    o.w = v.w * scale * gv.w;
    if (DO_SILU) {
        o.x = siluf(o.x); o.y = siluf(o.y); o.z = siluf(o.z); o.w = siluf(o.w);
    }
    ((float4*)(out + (size_t)row * 1024))[tid] = o;
}

// ---------------- plain split-K reduce (no bias) ----------------
__global__ void __launch_bounds__(256) reduce4_kernel(
    const float* __restrict__ P, float* __restrict__ out)
{
    const size_t i = (size_t)blockIdx.x * blockDim.x + threadIdx.x;   // float4 idx
    const size_t stride4 = (size_t)BATCH * MAMBA_DIM / 4;
    PDL_WAIT();
    float4 v = ((const float4*)P)[i];
#pragma unroll
    for (int s = 1; s < SPLITS; s++) {
        float4 t = ((const float4*)P)[i + s * stride4];
        v.x += t.x; v.y += t.y; v.z += t.z; v.w += t.w;
    }
    ((float4*)out)[i] = v;
}

// ---------------- B/C conv (once per batch, no redundancy) ----------------
__global__ void __launch_bounds__(256) conv_bc_kernel(
    const float* __restrict__ conv_state, const float* __restrict__ zx,
    const float* __restrict__ conv_w, const float* __restrict__ conv_b,
    float* __restrict__ out_conv, float* __restrict__ bc)
{
    const int b  = blockIdx.x;
    const int t  = threadIdx.x;
    const int ch = D_INNER + t;
    const size_t cidx = (size_t)b * CONV_DIM + ch;

    PDL_WAIT();

    float4 s  = ((const float4*)conv_state)[cidx];
    float  xn = zx[(size_t)b * D_IN_PROJ + D_INNER + ch];
    float4 ns = make_float4(s.y, s.z, s.w, xn);
    ((float4*)out_conv)[cidx] = ns;

    float4 w = ((const float4*)conv_w)[ch];
    float v = ns.x * w.x + ns.y * w.y + ns.z * w.z + ns.w * w.w + conv_b[ch];
    bc[b * BC_DIM + t] = siluf(v);
}

// ---------------- fused xh-conv + SSM update (round-11 optimum) ----------------
// one block per (b,h); 8 warps; warp w owns p rows w*8..w*8+7 in two batches of 4.
// 6 CTAs/SM (reg cap 42) — empirically the reg/occupancy optimum (r10/r11/r12).
__global__ void __launch_bounds__(256, 6) ssm_kernel(
    const float* __restrict__ ssm_state, const float* __restrict__ zx,
    const float* __restrict__ conv_state, const float* __restrict__ conv_w,
    const float* __restrict__ conv_b, const float* __restrict__ bc,
    const float* __restrict__ A_log, const float* __restrict__ dt_bias,
    const float* __restrict__ Dvec,
    float* __restrict__ out_ssm, float* __restrict__ out_conv,
    float* __restrict__ ybuf)
{
    const int bh = blockIdx.x;
    const int b  = bh >> 5;
    const int h  = bh & 31;
    const int tid  = threadIdx.x;
    const int lane = tid & 31;
    const int warp = tid >> 5;

    PDL_WAIT();

    const float* zxr = zx + (size_t)b * D_IN_PROJ;

    float dtraw = zxr[D_INNER + CONV_DIM + h] + dt_bias[h];
    float dtv = (dtraw > 20.f) ? dtraw : log1pf(expf(dtraw));
    float da  = expf(-expf(A_log[h]) * dtv);
    float Dh  = Dvec[h];

    __shared__ __align__(16) float sh_db[D_STATE];
    __shared__ __align__(16) float sh_c [D_STATE];
    __shared__ float sh_xh[HEADDIM];

    if (tid < 128) {
        sh_db[tid] = dtv * bc[b * BC_DIM + tid];
        sh_c [tid] = bc[b * BC_DIM + D_STATE + tid];
    } else if (tid < 192) {
        int p  = tid - 128;
        int ch = h * HEADDIM + p;
        size_t cidx = (size_t)b * CONV_DIM + ch;
        float4 s  = ((const float4*)conv_state)[cidx];
        float  xn = zxr[D_INNER + ch];
        float4 ns4 = make_float4(s.y, s.z, s.w, xn);
        ((float4*)out_conv)[cidx] = ns4;
        float4 w = ((const float4*)conv_w)[ch];
        float v = ns4.x * w.x + ns4.y * w.y + ns4.z * w.z + ns4.w * w.w + conv_b[ch];
        sh_xh[p] = siluf(v);
    }
    __syncthreads();

    const size_t base4 = (size_t)bh * HEADDIM * (D_STATE / 4);
    const float4* ss4 = (const float4*)ssm_state + base4;
    float4*       os4 = (float4*)out_ssm + base4;

    float4 c4  = ((const float4*)sh_c)[lane];
    float4 db4 = ((const float4*)sh_db)[lane];

#pragma unroll
    for (int half = 0; half < 2; half++) {
        const int p0 = warp * 8 + half * 4;

        float4 sv[4];
#pragma unroll
        for (int i = 0; i < 4; i++)
            sv[i] = __ldcs(&ss4[(p0 + i) * 32 + lane]);

#pragma unroll
        for (int i = 0; i < 4; i++) {
            int p = p0 + i;
            float xv = sh_xh[p];
            float4 ns;
            ns.x = fmaf(sv[i].x, da, xv * db4.x);
            ns.y = fmaf(sv[i].y, da, xv * db4.y);
            ns.z = fmaf(sv[i].z, da, xv * db4.z);
            ns.w = fmaf(sv[i].w, da, xv * db4.w);
            __stcs(&os4[p * 32 + lane], ns);

            float part = ns.x * c4.x + ns.y * c4.y + ns.z * c4.z + ns.w * c4.w;
#pragma unroll
            for (int o = 16; o; o >>= 1) part += __shfl_xor_sync(~0u, part, o);
            if (lane == 0) {
                float yv = part + Dh * xv;
                float z  = zxr[h * HEADDIM + p];
                ybuf[(size_t)b * D_INNER + h * HEADDIM + p] = yv * siluf(z);
            }
        }
    }
}

// ---------------- launch ----------------
static cudaLaunchAttribute g_pdl_attr[1];

template <typename F, typename... Args>
static inline void launch_pdl(F* func, dim3 grid, dim3 block, Args... args)
{
    g_pdl_attr[0].id = cudaLaunchAttributeProgrammaticStreamSerialization;
    g_pdl_attr[0].val.programmaticStreamSerializationAllowed = 1;
    cudaLaunchConfig_t cfg = {};
    cfg.gridDim = grid;
    cfg.blockDim = block;
    cfg.dynamicSmemBytes = 0;
    cfg.stream = 0;
    cfg.attrs = g_pdl_attr;
    cfg.numAttrs = 1;
    cudaLaunchKernelEx(&cfg, func, args...);
}

extern "C" void kernel_launch(void* const* d_in, const int* in_sizes, int n_in,
                              void* d_out, int out_size)
{
    const float* x          = (const float*)d_in[0];
    const float* conv_state = (const float*)d_in[1];
    const float* ssm_state  = (const float*)d_in[2];
    const float* w_in       = (const float*)d_in[3];
    const float* b_in       = (const float*)d_in[4];
    const float* g_in       = (const float*)d_in[5];
    const float* W_inproj   = (const float*)d_in[6];
    const float* conv_w     = (const float*)d_in[7];
    const float* conv_b     = (const float*)d_in[8];
    const float* A_log      = (const float*)d_in[9];
    const float* dt_bias    = (const float*)d_in[10];
    const float* Dvec       = (const float*)d_in[11];
    const float* W_mamba    = (const float*)d_in[12];
    const float* w_out      = (const float*)d_in[13];
    const float* b_out      = (const float*)d_in[14];
    const float* g_outnorm  = (const float*)d_in[15];

    float* out      = (float*)d_out;
    float* out_y    = out + OUT_Y_OFF;
    float* out_conv = out + OUT_CONV_OFF;
    float* out_ssm  = out + OUT_SSM_OFF;

    float *h, *zx, *bc, *ybuf, *t2, *part;
    cudaGetSymbolAddress((void**)&h,    g_h);
    cudaGetSymbolAddress((void**)&zx,   g_zx);
    cudaGetSymbolAddress((void**)&bc,   g_bc);
    cudaGetSymbolAddress((void**)&ybuf, g_ybuf);
    cudaGetSymbolAddress((void**)&t2,   g_t2);
    cudaGetSymbolAddress((void**)&part, g_part);

    const float* nullb = nullptr;

    // 1) split-K: part[s] = x @ w_in (slice s)   [512,1536]x[1536,1024]
    launch_pdl(gemm_tf32<128, 128, 2, 8, true>, dim3(8, 4, SPLITS), dim3(256),
               x, w_in, nullb, part, (int)BATCH, (int)MAMBA_DIM, (int)INPUT_DIM,
               (int)(INPUT_DIM / SPLITS));
    // 2) h = silu(rmsnorm(sum(part) + b_in, g_in))
    launch_pdl(reduce_rmsnorm_kernel<true>, dim3(BATCH), dim3(256),
               (const float*)part, b_in, g_in, h);
    // 3) zx = h @ W_inproj        [512,1024]x[1024,4384]  (140 blocks)
    launch_pdl(gemm_tf32<128, 128, 2, 8, false>,
               dim3((D_IN_PROJ + 127) / 128, BATCH / 128), dim3(256),
               (const float*)h, W_inproj, nullb, zx,
               (int)BATCH, (int)D_IN_PROJ, (int)MAMBA_DIM, (int)MAMBA_DIM);
    // 4) B/C conv once per batch (writes bc + its slice of out_conv)
    launch_pdl(conv_bc_kernel, dim3(BATCH), dim3(256),
               conv_state, (const float*)zx, conv_w, conv_b, out_conv, bc);
    // 5) fused xh-conv + SSM update (writes out_conv xh slice, out_ssm, ybuf)
    launch_pdl(ssm_kernel, dim3(BATCH * NHEADS), dim3(256),
               ssm_state, (const float*)zx, conv_state, conv_w, conv_b,
               (const float*)bc, A_log, dt_bias, Dvec, out_ssm, out_conv, ybuf);
    // 6) split-K: part[s] = ybuf @ W_mamba_out (slice s)  [512,2048]x[2048,1024]
    launch_pdl(gemm_tf32<128, 128, 2, 8, true>, dim3(8, 4, SPLITS), dim3(256),
               (const float*)ybuf, W_mamba, nullb, part,
               (int)BATCH, (int)MAMBA_DIM, (int)D_INNER, (int)(D_INNER / SPLITS));
    // 7) t2 = sum(part)
    launch_pdl(reduce4_kernel, dim3(BATCH), dim3(256), (const float*)part, t2);
    // 8) split-K: part[s] = t2 @ w_out (slice s)  [512,1024]x[1024,1024]
    launch_pdl(gemm_tf32<128, 128, 2, 8, true>, dim3(8, 4, SPLITS), dim3(256),
               (const float*)t2, w_out, nullb, part,
               (int)BATCH, (int)OUTPUT_DIM, (int)MAMBA_DIM, (int)(MAMBA_DIM / SPLITS));
    // 9) out_y = rmsnorm(sum(part) + b_out, g_outnorm)
    launch_pdl(reduce_rmsnorm_kernel<false>, dim3(BATCH), dim3(256),
               (const float*)part, b_out, g_outnorm, out_y);
}

// round 15
// speedup vs baseline: 1.1071x; 1.0058x over previous
#include <cuda_runtime.h>
#include <cuda_bf16.h>
#include <math.h>
#include <stdint.h>

// ---------------- problem constants ----------------
#define BATCH      512
#define INPUT_DIM  1536
#define MAMBA_DIM  1024
#define OUTPUT_DIM 1024
#define D_STATE    128
#define D_CONV     4
#define HEADDIM    64
#define D_INNER    2048
#define NHEADS     32
#define CONV_DIM   2304          // D_INNER + 2*D_STATE
#define D_IN_PROJ  4384          // 2*D_INNER + 2*D_STATE + NHEADS
#define EPS        1e-5f
#define SPLITS     4
#define BC_DIM     (2 * D_STATE)             // 256
#define TILE_BYTES (HEADDIM * D_STATE * 4)   // 32768 per (b,h) state tile

// output regions (floats)
#define OUT_Y_OFF    0
#define OUT_CONV_OFF (BATCH * OUTPUT_DIM)                       // 524288
#define OUT_SSM_OFF  (OUT_CONV_OFF + BATCH * CONV_DIM * D_CONV) // 5242880

// ---------------- PDL intrinsics (sm_90+) ----------------
#if defined(__CUDA_ARCH__) && (__CUDA_ARCH__ >= 900)
#define PDL_WAIT()    cudaGridDependencySynchronize()
#define PDL_TRIGGER() cudaTriggerProgrammaticLaunchCompletion()
#else
#define PDL_WAIT()
#define PDL_TRIGGER()
#endif

// ---------------- scratch (global device arrays, no allocation) ----------------
__device__ float g_h   [BATCH * MAMBA_DIM];            // silu(rmsnorm(...))
__device__ float g_zx  [BATCH * D_IN_PROJ];            // zxbcdt
__device__ float g_bc  [BATCH * BC_DIM];               // silu(conv) of B/C channels
__device__ float g_ybuf[BATCH * D_INNER];              // gated y before out proj
__device__ float g_t2  [BATCH * MAMBA_DIM];            // y@W_mamba_out
__device__ float g_part[SPLITS * BATCH * MAMBA_DIM];   // split-K partials (8MB)

// ---------------- helpers ----------------
__device__ __forceinline__ float siluf(float v) { return v / (1.f + expf(-v)); }

__device__ __forceinline__ uint32_t f2tf32(float f) {
    uint32_t u;
    asm("cvt.rna.tf32.f32 %0, %1;" : "=r"(u) : "f"(f));
    return u;
}

__device__ __forceinline__ void mma_tf32(float* c,
                                         uint32_t a0, uint32_t a1, uint32_t a2, uint32_t a3,
                                         uint32_t b0, uint32_t b1) {
    asm volatile(
        "mma.sync.aligned.m16n8k8.row.col.f32.tf32.tf32.f32 "
        "{%0,%1,%2,%3}, {%4,%5,%6,%7}, {%8,%9}, {%0,%1,%2,%3};"
        : "+f"(c[0]), "+f"(c[1]), "+f"(c[2]), "+f"(c[3])
        : "r"(a0), "r"(a1), "r"(a2), "r"(a3), "r"(b0), "r"(b1));
}

__device__ __forceinline__ void cp_async16(void* smem_dst, const void* gsrc) {
    uint32_t d = (uint32_t)__cvta_generic_to_shared(smem_dst);
    asm volatile("cp.async.cg.shared.global [%0], [%1], 16;\n" :: "r"(d), "l"(gsrc));
}
__device__ __forceinline__ void cp_async16z(void* smem_dst, const void* gsrc, int src_bytes) {
    uint32_t d = (uint32_t)__cvta_generic_to_shared(smem_dst);
    asm volatile("cp.async.cg.shared.global [%0], [%1], 16, %2;\n"
                 :: "r"(d), "l"(gsrc), "r"(src_bytes));
}
#define CP_COMMIT() asm volatile("cp.async.commit_group;\n" ::: "memory")
#define CP_WAIT1()  asm volatile("cp.async.wait_group 1;\n" ::: "memory")

// ---------------- mbarrier + 1D TMA bulk helpers ----------------
__device__ __forceinline__ uint32_t smem_u32(const void* p) {
    return (uint32_t)__cvta_generic_to_shared(p);
}
__device__ __forceinline__ void mbar_init(uint32_t mbar, uint32_t count) {
    asm volatile("mbarrier.init.shared.b64 [%0], %1;" :: "r"(mbar), "r"(count) : "memory");
}
__device__ __forceinline__ void mbar_expect_tx(uint32_t mbar, uint32_t bytes) {
    asm volatile("mbarrier.arrive.expect_tx.shared.b64 _, [%0], %1;"
                 :: "r"(mbar), "r"(bytes) : "memory");
}
__device__ __forceinline__ void bulk_g2s(uint32_t smem_dst, const void* gsrc,
                                         uint32_t bytes, uint32_t mbar) {
    asm volatile(
        "cp.async.bulk.shared::cta.global.mbarrier::complete_tx::bytes [%0], [%1], %2, [%3];"
        :: "r"(smem_dst), "l"(gsrc), "r"(bytes), "r"(mbar) : "memory");
}
__device__ __forceinline__ void mbar_wait_parity0(uint32_t mbar) {
    uint32_t done;
    do {
        asm volatile(
            "{\n\t.reg .pred p;\n\t"
            "mbarrier.try_wait.parity.shared.b64 p, [%1], %2;\n\t"
            "selp.b32 %0, 1, 0, p;\n\t}"
            : "=r"(done) : "r"(mbar), "r"(0u) : "memory");
    } while (!done);
}

// ---------------- TF32 tensor-core GEMM, 3-stage cp.async pipeline (round-9 proven) ----------------
template <int BM, int BN, int MI, int NI, bool SPLIT>
__global__ void __launch_bounds__(256) gemm_tf32(
    const float* __restrict__ A, const float* __restrict__ B,
    const float* __restrict__ bias, float* __restrict__ C,
    int M, int N, int K, int klen)
{
    constexpr int ASTR = 36;
    constexpr int BSTR = BN + 8;
    constexpr int ACH  = BM / 32;
    constexpr int BCH  = BN / 32;
    constexpr int STG  = 3;

    __shared__ __align__(16) float As[STG][BM][ASTR];
    __shared__ __align__(16) float Bs[STG][32][BSTR];

    const int tid  = threadIdx.x;
    const int lane = tid & 31;
    const int warp = tid >> 5;
    const int wm   = warp >> 1;
    const int wn   = warp & 1;
    const int gid  = lane >> 2;
    const int tig  = lane & 3;

    const int bm = blockIdx.y * BM;
    const int bn = blockIdx.x * BN;
    const int kb = SPLIT ? blockIdx.z * klen : 0;
    if (SPLIT) C += (size_t)blockIdx.z * M * N;
    const int m_warp = wm * (MI * 16);
    const int n_warp = wn * (NI * 8);

    auto issue_tile = [&](int t, int stg) {
        const int k0 = kb + t * 32;
#pragma unroll
        for (int i = 0; i < ACH; i++) {
            int id  = tid + 256 * i;
            int row = id >> 3;
            int c4  = (id & 7) * 4;
            cp_async16(&As[stg][row][c4], A + (size_t)(bm + row) * K + k0 + c4);
        }
#pragma unroll
        for (int i = 0; i < BCH; i++) {
            int id  = tid + 256 * i;
            int rw  = id / (BN / 4);
            int c   = (id % (BN / 4)) * 4;
            int col = bn + c;
            const float* src = B + (size_t)(k0 + rw) * N + (col < N ? col : 0);
            cp_async16z(&Bs[stg][rw][c], src, col < N ? 16 : 0);
        }
    };

    float acc[MI][NI][4];
#pragma unroll
    for (int mi = 0; mi < MI; mi++)
#pragma unroll
        for (int ni = 0; ni < NI; ni++)
#pragma unroll
            for (int j = 0; j < 4; j++) acc[mi][ni][j] = 0.f;

    const int ktiles = (SPLIT ? klen : K) / 32;

    // wait for producer's writes to be visible before first global read
    PDL_WAIT();

#pragma unroll
    for (int t = 0; t < 2; t++) {
        if (t < ktiles) issue_tile(t, t);
        CP_COMMIT();
    }

    for (int t = 0; t < ktiles; t++) {
        CP_WAIT1();
        __syncthreads();

        if (t + 2 < ktiles) issue_tile(t + 2, (t + 2) % STG);
        CP_COMMIT();

        const int st = t % STG;
#pragma unroll
        for (int s = 0; s < 4; s++) {
            uint32_t af[MI][4], bf[NI][2];
#pragma unroll
            for (int mi = 0; mi < MI; mi++) {
                int r0 = m_warp + mi * 16 + gid;
                int kk = s * 8 + tig;
                af[mi][0] = f2tf32(As[st][r0][kk]);
                af[mi][1] = f2tf32(As[st][r0 + 8][kk]);
                af[mi][2] = f2tf32(As[st][r0][kk + 4]);
                af[mi][3] = f2tf32(As[st][r0 + 8][kk + 4]);
            }
#pragma unroll
            for (int ni = 0; ni < NI; ni++) {
                int n0 = n_warp + ni * 8 + gid;
                int kk = s * 8 + tig;
                bf[ni][0] = f2tf32(Bs[st][kk][n0]);
                bf[ni][1] = f2tf32(Bs[st][kk + 4][n0]);
            }
#pragma unroll
            for (int mi = 0; mi < MI; mi++)
#pragma unroll
                for (int ni = 0; ni < NI; ni++)
                    mma_tf32(acc[mi][ni], af[mi][0], af[mi][1], af[mi][2], af[mi][3],
                             bf[ni][0], bf[ni][1]);
        }
    }

    // allow dependents to start launching while the epilogue drains
    PDL_TRIGGER();

    // epilogue
#pragma unroll
    for (int mi = 0; mi < MI; mi++) {
#pragma unroll
        for (int ni = 0; ni < NI; ni++) {
            int row = bm + m_warp + mi * 16 + gid;
            int col = bn + n_warp + ni * 8 + tig * 2;
            if (col < N) {
                float bx = 0.f, by = 0.f;
                if (!SPLIT && bias) { bx = bias[col]; by = bias[col + 1]; }
                float2 o0 = make_float2(acc[mi][ni][0] + bx, acc[mi][ni][1] + by);
                float2 o1 = make_float2(acc[mi][ni][2] + bx, acc[mi][ni][3] + by);
                *(float2*)(C + (size_t)row * N + col)       = o0;
                *(float2*)(C + (size_t)(row + 8) * N + col) = o1;
            }
        }
    }
}

// ---------------- fused split-K reduce + bias + rmsnorm (+ optional silu), N=1024 ----------------
template <bool DO_SILU>
__global__ void __launch_bounds__(256) reduce_rmsnorm_kernel(
    const float* __restrict__ P, const float* __restrict__ bias,
    const float* __restrict__ g, float* __restrict__ out)
{
    const int row = blockIdx.x;
    const int tid = threadIdx.x;
    const size_t stride = (size_t)BATCH * MAMBA_DIM;

    PDL_WAIT();

    float4 v = ((const float4*)(P + (size_t)row * 1024))[tid];
#pragma unroll
    for (int s = 1; s < SPLITS; s++) {
        float4 t = ((const float4*)(P + s * stride + (size_t)row * 1024))[tid];
        v.x += t.x; v.y += t.y; v.z += t.z; v.w += t.w;
    }
    float4 bv = ((const float4*)bias)[tid];
    v.x += bv.x; v.y += bv.y; v.z += bv.z; v.w += bv.w;

    float ss = v.x * v.x + v.y * v.y + v.z * v.z + v.w * v.w;
    const int lane = tid & 31, warp = tid >> 5;
    __shared__ float red[8];
#pragma unroll
    for (int o = 16; o; o >>= 1) ss += __shfl_xor_sync(~0u, ss, o);
    if (lane == 0) red[warp] = ss;
    __syncthreads();
    if (warp == 0) {
        float t = (lane < 8) ? red[lane] : 0.f;
#pragma unroll
        for (int o = 4; o; o >>= 1) t += __shfl_xor_sync(~0u, t, o);
        if (lane == 0) red[0] = t;
    }
    __syncthreads();
    float scale = rsqrtf(red[0] * (1.f / 1024.f) + EPS);

    float4 gv = ((const float4*)g)[tid];
    float4 o;
    o.x = v.x * scale * gv.x;
    o.y = v.y * scale * gv.y;
    o.z = v.z * scale * gv.z;
    o.w = v.w * scale * gv.w;
    if (DO_SILU) {
        o.x = siluf(o.x); o.y = siluf(o.y); o.z = siluf(o.z); o.w = siluf(o.w);
    }
    ((float4*)(out + (size_t)row * 1024))[tid] = o;
}

// ---------------- plain split-K reduce (no bias) ----------------
__global__ void __launch_bounds__(256) reduce4_kernel(
    const float* __restrict__ P, float* __restrict__ out)
{
    const size_t i = (size_t)blockIdx.x * blockDim.x + threadIdx.x;   // float4 idx
    const size_t stride4 = (size_t)BATCH * MAMBA_DIM / 4;
    PDL_WAIT();
    float4 v = ((const float4*)P)[i];
#pragma unroll
    for (int s = 1; s < SPLITS; s++) {
        float4 t = ((const float4*)P)[i + s * stride4];
        v.x += t.x; v.y += t.y; v.z += t.z; v.w += t.w;
    }
    ((float4*)out)[i] = v;
}

// ---------------- B/C conv (once per batch, no redundancy) ----------------
__global__ void __launch_bounds__(256) conv_bc_kernel(
    const float* __restrict__ conv_state, const float* __restrict__ zx,
    const float* __restrict__ conv_w, const float* __restrict__ conv_b,
    float* __restrict__ out_conv, float* __restrict__ bc)
{
    const int b  = blockIdx.x;
    const int t  = threadIdx.x;
    const int ch = D_INNER + t;
    const size_t cidx = (size_t)b * CONV_DIM + ch;

    PDL_WAIT();

    float4 s  = ((const float4*)conv_state)[cidx];
    float  xn = zx[(size_t)b * D_IN_PROJ + D_INNER + ch];
    float4 ns = make_float4(s.y, s.z, s.w, xn);
    ((float4*)out_conv)[cidx] = ns;

    float4 w = ((const float4*)conv_w)[ch];
    float v = ns.x * w.x + ns.y * w.y + ns.z * w.z + ns.w * w.w + conv_b[ch];
    bc[b * BC_DIM + t] = siluf(v);
}

// ---------------- fused xh-conv + SSM update, TMA bulk state load ----------------
// one block per (b,h); 8 warps. The 32KB contiguous state tile is fetched by a
// single cp.async.bulk issued BEFORE the PDL wait (ssm_state is a harness input,
// independent of upstream kernels) — the state stream overlaps the dependency
// wait and the conv preamble. Compute reads the tile from smem (conflict-free
// LDS, lane stride 16B); stores remain streaming STG.128. Math order identical
// to the round-11/13 optimum.
__global__ void __launch_bounds__(256, 6) ssm_kernel(
    const float* __restrict__ ssm_state, const float* __restrict__ zx,
    const float* __restrict__ conv_state, const float* __restrict__ conv_w,
    const float* __restrict__ conv_b, const float* __restrict__ bc,
    const float* __restrict__ A_log, const float* __restrict__ dt_bias,
    const float* __restrict__ Dvec,
    float* __restrict__ out_ssm, float* __restrict__ out_conv,
    float* __restrict__ ybuf)
{
    __shared__ __align__(128) float4 tile4[HEADDIM * (D_STATE / 4)];  // 32KB
    __shared__ __align__(8)  unsigned long long mbar;
    __shared__ __align__(16) float sh_db[D_STATE];
    __shared__ __align__(16) float sh_c [D_STATE];
    __shared__ float sh_xh[HEADDIM];

    const int bh = blockIdx.x;
    const int b  = bh >> 5;
    const int h  = bh & 31;
    const int tid  = threadIdx.x;
    const int lane = tid & 31;
    const int warp = tid >> 5;

    const size_t base4 = (size_t)bh * HEADDIM * (D_STATE / 4);
    const uint32_t mb = smem_u32(&mbar);

    // kick off the state tile load immediately (input tensor: no PDL wait needed)
    if (tid == 0) {
        mbar_init(mb, 1);
        mbar_expect_tx(mb, TILE_BYTES);
        bulk_g2s(smem_u32(tile4), (const float4*)ssm_state + base4, TILE_BYTES, mb);
    }

    // now wait for upstream kernels (zx from gemm3, bc/out_conv from conv_bc)
    PDL_WAIT();

    const float* zxr = zx + (size_t)b * D_IN_PROJ;

    float dtraw = zxr[D_INNER + CONV_DIM + h] + dt_bias[h];
    float dtv = (dtraw > 20.f) ? dtraw : log1pf(expf(dtraw));
    float da  = expf(-expf(A_log[h]) * dtv);
    float Dh  = Dvec[h];

    if (tid < 128) {
        sh_db[tid] = dtv * bc[b * BC_DIM + tid];
        sh_c [tid] = bc[b * BC_DIM + D_STATE + tid];
    } else if (tid < 192) {
        int p  = tid - 128;
        int ch = h * HEADDIM + p;
        size_t cidx = (size_t)b * CONV_DIM + ch;
        float4 s  = ((const float4*)conv_state)[cidx];
        float  xn = zxr[D_INNER + ch];
        float4 ns4 = make_float4(s.y, s.z, s.w, xn);
        ((float4*)out_conv)[cidx] = ns4;
        float4 w = ((const float4*)conv_w)[ch];
        float v = ns4.x * w.x + ns4.y * w.y + ns4.z * w.z + ns4.w * w.w + conv_b[ch];
        sh_xh[p] = siluf(v);
    }
    __syncthreads();          // mbar init + preamble smem visible to all
    mbar_wait_parity0(mb);    // state tile landed

    float4* os4 = (float4*)out_ssm + base4;

    float4 c4  = ((const float4*)sh_c)[lane];
    float4 db4 = ((const float4*)sh_db)[lane];

#pragma unroll
    for (int half = 0; half < 2; half++) {
        const int p0 = warp * 8 + half * 4;

        float4 sv[4];
#pragma unroll
        for (int i = 0; i < 4; i++)
            sv[i] = tile4[(p0 + i) * 32 + lane];

#pragma unroll
        for (int i = 0; i < 4; i++) {
            int p = p0 + i;
            float xv = sh_xh[p];
            float4 ns;
            ns.x = fmaf(sv[i].x, da, xv * db4.x);
            ns.y = fmaf(sv[i].y, da, xv * db4.y);
            ns.z = fmaf(sv[i].z, da, xv * db4.z);
            ns.w = fmaf(sv[i].w, da, xv * db4.w);
            __stcs(&os4[p * 32 + lane], ns);

            float part = ns.x * c4.x + ns.y * c4.y + ns.z * c4.z + ns.w * c4.w;
#pragma unroll
            for (int o = 16; o; o >>= 1) part += __shfl_xor_sync(~0u, part, o);
            if (lane == 0) {
                float yv = part + Dh * xv;
                float z  = zxr[h * HEADDIM + p];
                ybuf[(size_t)b * D_INNER + h * HEADDIM + p] = yv * siluf(z);
            }
        }
    }
}

// ---------------- launch ----------------
static cudaLaunchAttribute g_pdl_attr[1];

template <typename F, typename... Args>
static inline void launch_pdl(F* func, dim3 grid, dim3 block, Args... args)
{
    g_pdl_attr[0].id = cudaLaunchAttributeProgrammaticStreamSerialization;
    g_pdl_attr[0].val.programmaticStreamSerializationAllowed = 1;
    cudaLaunchConfig_t cfg = {};
    cfg.gridDim = grid;
    cfg.blockDim = block;
    cfg.dynamicSmemBytes = 0;
    cfg.stream = 0;
    cfg.attrs = g_pdl_attr;
    cfg.numAttrs = 1;
    cudaLaunchKernelEx(&cfg, func, args...);
}

extern "C" void kernel_launch(void* const* d_in, const int* in_sizes, int n_in,
                              void* d_out, int out_size)
{
    const float* x          = (const float*)d_in[0];
    const float* conv_state = (const float*)d_in[1];
    const float* ssm_state  = (const float*)d_in[2];
    const float* w_in       = (const float*)d_in[3];
    const float* b_in       = (const float*)d_in[4];
    const float* g_in       = (const float*)d_in[5];
    const float* W_inproj   = (const float*)d_in[6];
    const float* conv_w     = (const float*)d_in[7];
    const float* conv_b     = (const float*)d_in[8];
    const float* A_log      = (const float*)d_in[9];
    const float* dt_bias    = (const float*)d_in[10];
    const float* Dvec       = (const float*)d_in[11];
    const float* W_mamba    = (const float*)d_in[12];
    const float* w_out      = (const float*)d_in[13];
    const float* b_out      = (const float*)d_in[14];
    const float* g_outnorm  = (const float*)d_in[15];

    float* out      = (float*)d_out;
    float* out_y    = out + OUT_Y_OFF;
    float* out_conv = out + OUT_CONV_OFF;
    float* out_ssm  = out + OUT_SSM_OFF;

    float *h, *zx, *bc, *ybuf, *t2, *part;
    cudaGetSymbolAddress((void**)&h,    g_h);
    cudaGetSymbolAddress((void**)&zx,   g_zx);
    cudaGetSymbolAddress((void**)&bc,   g_bc);
    cudaGetSymbolAddress((void**)&ybuf, g_ybuf);
    cudaGetSymbolAddress((void**)&t2,   g_t2);
    cudaGetSymbolAddress((void**)&part, g_part);

    const float* nullb = nullptr;

    // 1) split-K: part[s] = x @ w_in (slice s)   [512,1536]x[1536,1024]
    launch_pdl(gemm_tf32<128, 128, 2, 8, true>, dim3(8, 4, SPLITS), dim3(256),
               x, w_in, nullb, part, (int)BATCH, (int)MAMBA_DIM, (int)INPUT_DIM,
               (int)(INPUT_DIM / SPLITS));
    // 2) h = silu(rmsnorm(sum(part) + b_in, g_in))
    launch_pdl(reduce_rmsnorm_kernel<true>, dim3(BATCH), dim3(256),
               (const float*)part, b_in, g_in, h);
    // 3) zx = h @ W_inproj        [512,1024]x[1024,4384]  (140 blocks)
    launch_pdl(gemm_tf32<128, 128, 2, 8, false>,
               dim3((D_IN_PROJ + 127) / 128, BATCH / 128), dim3(256),
               (const float*)h, W_inproj, nullb, zx,
               (int)BATCH, (int)D_IN_PROJ, (int)MAMBA_DIM, (int)MAMBA_DIM);
    // 4) B/C conv once per batch (writes bc + its slice of out_conv)
    launch_pdl(conv_bc_kernel, dim3(BATCH), dim3(256),
               conv_state, (const float*)zx, conv_w, conv_b, out_conv, bc);
    // 5) fused xh-conv + SSM update (TMA state load; writes out_conv xh slice,
    //    out_ssm, gated ybuf)
    launch_pdl(ssm_kernel, dim3(BATCH * NHEADS), dim3(256),
               ssm_state, (const float*)zx, conv_state, conv_w, conv_b,
               (const float*)bc, A_log, dt_bias, Dvec, out_ssm, out_conv, ybuf);
    // 6) split-K: part[s] = ybuf @ W_mamba_out (slice s)  [512,2048]x[2048,1024]
    launch_pdl(gemm_tf32<128, 128, 2, 8, true>, dim3(8, 4, SPLITS), dim3(256),
               (const float*)ybuf, W_mamba, nullb, part,
               (int)BATCH, (int)MAMBA_DIM, (int)D_INNER, (int)(D_INNER / SPLITS));
    // 7) t2 = sum(part)
    launch_pdl(reduce4_kernel, dim3(BATCH), dim3(256), (const float*)part, t2);
    // 8) split-K: part[s] = t2 @ w_out (slice s)  [512,1024]x[1024,1024]
    launch_pdl(gemm_tf32<128, 128, 2, 8, true>, dim3(8, 4, SPLITS), dim3(256),
               (const float*)t2, w_out, nullb, part,
               (int)BATCH, (int)OUTPUT_DIM, (int)MAMBA_DIM, (int)(MAMBA_DIM / SPLITS));
    // 9) out_y = rmsnorm(sum(part) + b_out, g_outnorm)
    launch_pdl(reduce_rmsnorm_kernel<false>, dim3(BATCH), dim3(256),
               (const float*)part, b_out, g_outnorm, out_y);
}